// round 9
// baseline (speedup 1.0000x reference)
#include <cuda_runtime.h>
#include <cstdint>

#define Bb 8
#define Nn 2048
#define Mm 256
#define Qq 16384
#define Dd 32
#define Rr 16
#define Kk 16
#define Hh 64
#define LAM 5.0f
#define NITER 20
#define RAD 0.005859375f   // 1.5/256 exact in binary

// ---------------- scratch (device globals; no allocation allowed) ----------
__device__ float g_c0[Bb*Mm*Dd];     // c_loc (gvec added inside cg)
__device__ float g_c [Bb*Mm*Dd];
__device__ float g_gvec[Bb*Dd];

__device__ __forceinline__ float warp_sum(float v) {
#pragma unroll
    for (int o = 16; o; o >>= 1) v += __shfl_xor_sync(0xffffffffu, v, o);
    return v;
}

__device__ __forceinline__ unsigned smem_u32(const void* p) {
    unsigned a;
    asm("{ .reg .u64 t; cvta.to.shared.u64 t, %1; cvt.u32.u64 %0, t; }"
        : "=r"(a) : "l"(p));
    return a;
}

// store 4 bytes into peer CTA (rank) smem at the address corresponding to laddr
__device__ __forceinline__ void st_remote(unsigned laddr, unsigned rank, float v) {
    unsigned r;
    asm volatile("mapa.shared::cluster.u32 %0, %1, %2;" : "=r"(r) : "r"(laddr), "r"(rank));
    asm volatile("st.shared::cluster.f32 [%0], %1;" :: "r"(r), "f"(v) : "memory");
}

__device__ __forceinline__ void cluster_sync_() {
    asm volatile("barrier.cluster.arrive.aligned;" ::: "memory");  // release
    asm volatile("barrier.cluster.wait.aligned;"   ::: "memory");  // acquire
}

// ---------------- kernel 1: fused gvec (blocks 0-7) + encoder --------------
__global__ __launch_bounds__(256) void fe_kernel(
    const float* __restrict__ xs, const float* __restrict__ us,
    const float* __restrict__ centers, const int* __restrict__ idx,
    const float* __restrict__ W1, const float* __restrict__ b1,
    const float* __restrict__ W2, const float* __restrict__ b2,
    const float* __restrict__ W3, const float* __restrict__ b3,
    const float* __restrict__ Wg1, const float* __restrict__ bg1,
    const float* __restrict__ Wg2, const float* __restrict__ bg2)
{
    __shared__ float sW2T[64*68];      // W2 transposed, padded rows
    __shared__ float sh1[4][16*68];    // per-sub h1[k][i]
    __shared__ float srel[4][16], su[4][16], shbar[4][64];
    __shared__ float sW1[128];
    __shared__ float sp[256];          // gvec partials
    __shared__ float sg[64];

    int t = threadIdx.x;

    if (blockIdx.x < 8) {              // ---- gvec branch ----
        int b = blockIdx.x;
        int h = t & 63, grp = t >> 6;
        float w0 = Wg1[h], w1 = Wg1[Hh+h], bb = bg1[h];
        const float* xp = xs + b*Nn;
        const float* up = us + b*Nn;
        float acc = 0.f;
        int n0 = grp * (Nn/4);
        for (int n = n0; n < n0 + Nn/4; n++)
            acc += fmaxf(fmaf(xp[n], w0, fmaf(up[n], w1, bb)), 0.f);
        sp[t] = acc;
        __syncthreads();
        if (t < Hh) sg[t] = (sp[t] + sp[64+t] + sp[128+t] + sp[192+t]) * (1.0f/Nn);
        __syncthreads();
        if (t < Dd) {
            float a = bg2[t];
            for (int hh = 0; hh < Hh; hh++) a = fmaf(sg[hh], Wg2[hh*Dd + t], a);
            g_gvec[b*Dd + t] = a;
        }
        return;
    }

    // ---- encoder branch: 4 m values per block ----
    int blk = blockIdx.x - 8;
    int b = blk >> 6;          // 64 blocks per batch
    int mg = blk & 63;
    int sub = t >> 6, h = t & 63;
    int m = mg*4 + sub;

    if (t < 128) sW1[t] = W1[t];
    // cooperative W2 transpose: coalesced float4 gmem reads, scattered STS
    for (int i4 = t; i4 < 1024; i4 += 256) {
        float4 v = ((const float4*)W2)[i4];
        int lin = i4 * 4;
        int i = lin >> 6;      // W2 row
        int j = lin & 63;      // W2 col
        sW2T[(j+0)*68 + i] = v.x;
        sW2T[(j+1)*68 + i] = v.y;
        sW2T[(j+2)*68 + i] = v.z;
        sW2T[(j+3)*68 + i] = v.w;
    }
    if (h < 16) {
        int sidx = idx[m*Kk + h];
        srel[sub][h] = (xs[b*Nn + sidx] - centers[m]) / RAD;
        su[sub][h]   = us[b*Nn + sidx];
    }
    __syncthreads();

    {   // h1: thread h = hidden unit
        float wa = sW1[h], wb = sW1[64+h], bb = b1[h];
#pragma unroll
        for (int k = 0; k < 16; k++)
            sh1[sub][k*68 + h] = fmaxf(fmaf(srel[sub][k], wa, fmaf(su[sub][k], wb, bb)), 0.f);
    }
    __syncthreads();

    {   // h2 = relu(h1 @ W2 + b2); mean over k
        float acc[16];
        float bb = b2[h];
#pragma unroll
        for (int k = 0; k < 16; k++) acc[k] = bb;
        for (int i = 0; i < 64; i += 4) {
            float4 wq = *(const float4*)&sW2T[h*68 + i];
#pragma unroll
            for (int k = 0; k < 16; k++) {
                float4 hq = *(const float4*)&sh1[sub][k*68 + i];
                acc[k] = fmaf(hq.x, wq.x, acc[k]);
                acc[k] = fmaf(hq.y, wq.y, acc[k]);
                acc[k] = fmaf(hq.z, wq.z, acc[k]);
                acc[k] = fmaf(hq.w, wq.w, acc[k]);
            }
        }
        float s = 0.f;
#pragma unroll
        for (int k = 0; k < 16; k++) s += fmaxf(acc[k], 0.f);
        shbar[sub][h] = s * 0.0625f;
    }
    __syncthreads();

    if (h < 32) {
        float v = b3[h];
        for (int j = 0; j < 64; j++) v = fmaf(shbar[sub][j], W3[j*Dd + h], v);
        g_c0[(b*Mm + m)*Dd + h] = v;   // c_loc only; gvec added in cg
    }
}

// ---------------- CG edge pass: phase1 smem rows, phase2 register columns ---
__device__ __forceinline__ void edge_pass2(
    const float* __restrict__ sRS, const float* __restrict__ sRD,
    const float* __restrict__ sP, float* __restrict__ sGs, float* __restrict__ sGd,
    float* __restrict__ sRe, int nE, int wid, int lane,
    const float (&cS0)[16], const float (&cD0)[16],
    const float (&cS1)[16], const float (&cD1)[16])
{
    int rho = lane >> 1, h = lane & 1;
    // ---- phase 1: r_e = Rs@p_src - Rd@p_dst (rows from smem) ----
    for (int el = wid; el < nE; el += 16) {
        const float* bs  = sRS + el*528;
        const float* bd  = sRD + el*528;
        const float* ps  = sP + el*32 + 16*h;
        const float* rs_ = bs + rho*33 + 16*h;
        const float* rd_ = bd + rho*33 + 16*h;
        float a0 = 0.f, a1 = 0.f, a2 = 0.f, a3 = 0.f;
#pragma unroll
        for (int i = 0; i < 16; i += 4) {
            a0 = fmaf(rs_[i+0], ps[i+0], a0);
            a1 = fmaf(rs_[i+1], ps[i+1], a1);
            a2 = fmaf(rs_[i+2], ps[i+2], a2);
            a3 = fmaf(rs_[i+3], ps[i+3], a3);
            a0 = fmaf(rd_[i+0], -ps[32+i+0], a0);
            a1 = fmaf(rd_[i+1], -ps[32+i+1], a1);
            a2 = fmaf(rd_[i+2], -ps[32+i+2], a2);
            a3 = fmaf(rd_[i+3], -ps[32+i+3], a3);
        }
        float acc = (a0 + a1) + (a2 + a3);
        acc += __shfl_xor_sync(0xffffffffu, acc, 1);
        if (h == 0) sRe[el*16 + rho] = acc;
    }
    __syncwarp();
    // ---- phase 2: gs/gd columns from registers ----
    {
        int e0 = wid;
        float g0=0.f, g1=0.f, d0=0.f, d1=0.f;
#pragma unroll
        for (int q = 0; q < 16; q += 2) {
            float r0 = sRe[e0*16 + q], r1 = sRe[e0*16 + q + 1];
            g0 = fmaf(cS0[q],   r0, g0);
            g1 = fmaf(cS0[q+1], r1, g1);
            d0 = fmaf(cD0[q],   r0, d0);
            d1 = fmaf(cD0[q+1], r1, d1);
        }
        sGs[e0*32 + lane] = g0 + g1;
        sGd[e0*32 + lane] = d0 + d1;
    }
    {
        int e1 = wid + 16;
        if (e1 < nE) {
            float g0=0.f, g1=0.f, d0=0.f, d1=0.f;
#pragma unroll
            for (int q = 0; q < 16; q += 2) {
                float r0 = sRe[e1*16 + q], r1 = sRe[e1*16 + q + 1];
                g0 = fmaf(cS1[q],   r0, g0);
                g1 = fmaf(cS1[q+1], r1, g1);
                d0 = fmaf(cD1[q],   r0, d0);
                d1 = fmaf(cD1[q+1], r1, d1);
            }
            sGs[e1*32 + lane] = g0 + g1;
            sGd[e1*32 + lane] = d0 + d1;
        }
    }
    {
        int e2 = wid + 32;                 // only warp 0 in middle CTAs
        if (e2 < nE) {
            const float* bs = sRS + e2*528;
            const float* bd = sRD + e2*528;
            float g0=0.f, g1=0.f, d0=0.f, d1=0.f;
#pragma unroll
            for (int q = 0; q < 16; q += 2) {
                float r0 = sRe[e2*16 + q], r1 = sRe[e2*16 + q + 1];
                g0 = fmaf(bs[q*33 + lane],     r0, g0);
                g1 = fmaf(bs[(q+1)*33 + lane], r1, g1);
                d0 = fmaf(bd[q*33 + lane],     r0, d0);
                d1 = fmaf(bd[(q+1)*33 + lane], r1, d1);
            }
            sGs[e2*32 + lane] = g0 + g1;
            sGd[e2*32 + lane] = d0 + d1;
        }
    }
}

// ---------------- kernel 2: persistent cluster CG (8 clusters x 8 CTAs) -----
// smem layout (float offsets)
#define SM_RS  0
#define SM_RD  17424
#define SM_P   (17424*2)          // 34848
#define SM_X   (SM_P + 1088)
#define SM_R   (SM_X + 1024)
#define SM_AP  (SM_R + 1024)
#define SM_GS  (SM_AP + 1024)     // 33*32
#define SM_GD  (SM_GS + 1056)
#define SM_RE  (SM_GD + 1056)     // 33*16
#define SM_RED (SM_RE + 528)      // 16 warp partials
#define SM_S0  (SM_RED + 16)      // incoming rs partials [8]
#define SM_S1  (SM_S0 + 8)        // incoming pAp partials [8]
#define SM_HL  (SM_S1 + 8)        // incoming left-halo r [32]
#define SM_HR  (SM_HL + 32)       // incoming right-halo r [32]
#define SM_TOT_FLOATS (SM_HR + 32)
#define SMEM_CG_BYTES (SM_TOT_FLOATS * 4)

__global__ __launch_bounds__(512, 1) __cluster_dims__(8, 1, 1)
void cg_kernel(const float* __restrict__ Rsrc, const float* __restrict__ Rdst,
               float* __restrict__ out)
{
    extern __shared__ float sm[];
    float* sRS  = sm + SM_RS;
    float* sRD  = sm + SM_RD;
    float* sP   = sm + SM_P;
    float* sX   = sm + SM_X;
    float* sR   = sm + SM_R;
    float* sAp  = sm + SM_AP;
    float* sGs  = sm + SM_GS;
    float* sGd  = sm + SM_GD;
    float* sRe  = sm + SM_RE;
    float* sRed = sm + SM_RED;
    float* sS0  = sm + SM_S0;
    float* sS1  = sm + SM_S1;
    float* sHL  = sm + SM_HL;
    float* sHR  = sm + SM_HR;

    int t = threadIdx.x, wid = t >> 5, lane = t & 31;
    int blk = blockIdx.x;
    int b = blk >> 3, c = blk & 7;          // cluster = batch, rank = c
    int m0 = c * 32;
    int mLo = (c > 0) ? m0 - 1 : 0;
    int mHi = (c < 7) ? m0 + 32 : 255;
    int nExt = mHi - mLo + 1;
    int eLo = (c > 0) ? m0 - 1 : 0;
    int eHi = (c < 7) ? m0 + 31 : 254;
    int nE = eHi - eLo + 1;
    int ownOff = (m0 - mLo) * 32;

    unsigned smb = smem_u32(sm);
    unsigned aS0 = smb + (SM_S0 + c) * 4;   // slot c in peers' rs array
    unsigned aS1 = smb + (SM_S1 + c) * 4;   // slot c in peers' pAp array
    unsigned aHL = smb + SM_HL * 4;
    unsigned aHR = smb + SM_HR * 4;

    // ---- load R tiles into padded smem (resident for all iterations) ----
    for (int i = t; i < nE*512; i += 512) {
        int el = i >> 9, rem = i & 511;
        int rho = rem >> 5, d = rem & 31;
        int g = (eLo + el)*512 + rem;
        sRS[el*528 + rho*33 + d] = Rsrc[g];
        sRD[el*528 + rho*33 + d] = Rdst[g];
    }
    // c0 extended = c_loc + gvec broadcast
    const float* c0b = g_c0 + b*Mm*Dd;
    const float* gvb = g_gvec + b*Dd;
    for (int i = t; i < nExt*32; i += 512)
        sP[i] = c0b[mLo*32 + i] + gvb[i & 31];
    __syncthreads();

    // register-resident R columns for this warp's edges
    float cS0[16], cD0[16], cS1[16], cD1[16];
    {
        int e0 = wid;
#pragma unroll
        for (int q = 0; q < 16; q++) {
            cS0[q] = sRS[e0*528 + q*33 + lane];
            cD0[q] = sRD[e0*528 + q*33 + lane];
        }
        int e1 = wid + 16;
        if (e1 < nE) {
#pragma unroll
            for (int q = 0; q < 16; q++) {
                cS1[q] = sRS[e1*528 + q*33 + lane];
                cD1[q] = sRD[e1*528 + q*33 + lane];
            }
        } else {
#pragma unroll
            for (int q = 0; q < 16; q++) { cS1[q] = 0.f; cD1[q] = 0.f; }
        }
    }

    for (int i = t; i < 1024; i += 512) sX[i] = sP[ownOff + i];
    // write c0 output segment (own nodes)
    for (int i = t; i < 1024; i += 512)
        out[Bb*Qq + (b*Mm + m0)*32 + i] = sP[ownOff + i];

    // ---- prologue: r0 = -LAM * L(c0) ----
    edge_pass2(sRS, sRD, sP, sGs, sGd, sRe, nE, wid, lane, cS0, cD0, cS1, cD1);
    __syncthreads();
    {
        float part = 0.f;
        for (int i = t; i < 1024; i += 512) {
            int d = i & 31;
            int m = m0 + (i >> 5);
            float gs = (m <= 254) ? sGs[(m - eLo)*32 + d] : 0.f;
            float gd = (m >= 1)   ? sGd[(m - 1 - eLo)*32 + d] : 0.f;
            float rv = -LAM * (gs - gd);
            sR[i] = rv;
            part = fmaf(rv, rv, part);
        }
        part = warp_sum(part);
        if (lane == 0) sRed[wid] = part;
    }
    __syncthreads();
    if (t < 8) {
        float tot = 0.f;
#pragma unroll
        for (int j = 0; j < 16; j++) tot += sRed[j];
        st_remote(aS0, (unsigned)t, tot);
    }
    if (c > 0 && t < 32)              st_remote(aHR + t*4, (unsigned)(c-1), sR[t]);
    if (c < 7 && t >= 32 && t < 64) { int l = t - 32;
                                      st_remote(aHL + l*4, (unsigned)(c+1), sR[31*32 + l]); }
    cluster_sync_();

    float rs_prev = 1.f;
    for (int k = 0; k < NITER; k++) {
        // ---- phase A: beta, p update, Ap, partial p.Ap ----
        float rs_k = 0.f;
#pragma unroll
        for (int j = 0; j < 8; j++) rs_k += sS0[j];
        float beta = (k == 0) ? 0.f : rs_k / (rs_prev + 1e-12f);

        for (int i = t; i < 1024; i += 512)
            sP[ownOff + i] = fmaf(beta, sP[ownOff + i], sR[i]);
        if (c > 0 && t < 32)
            sP[t] = fmaf(beta, sP[t], sHL[t]);
        if (c < 7 && t >= 32 && t < 64) { int l = t - 32;
            sP[(nExt-1)*32 + l] = fmaf(beta, sP[(nExt-1)*32 + l], sHR[l]); }
        __syncthreads();
        edge_pass2(sRS, sRD, sP, sGs, sGd, sRe, nE, wid, lane, cS0, cD0, cS1, cD1);
        __syncthreads();
        {
            float pap = 0.f;
            for (int i = t; i < 1024; i += 512) {
                int d = i & 31;
                int m = m0 + (i >> 5);
                float gs = (m <= 254) ? sGs[(m - eLo)*32 + d] : 0.f;
                float gd = (m >= 1)   ? sGd[(m - 1 - eLo)*32 + d] : 0.f;
                float pv = sP[ownOff + i];
                float ap = fmaf(LAM, gs - gd, pv);
                sAp[i] = ap;
                pap = fmaf(ap, pv, pap);
            }
            pap = warp_sum(pap);
            if (lane == 0) sRed[wid] = pap;
        }
        __syncthreads();
        if (t < 8) {
            float tot = 0.f;
#pragma unroll
            for (int j = 0; j < 16; j++) tot += sRed[j];
            st_remote(aS1, (unsigned)t, tot);
        }
        cluster_sync_();

        // ---- phase B: alpha, x/r update, partial ||r||^2, push rs + halo ----
        float pap_tot = 0.f;
#pragma unroll
        for (int j = 0; j < 8; j++) pap_tot += sS1[j];
        float alpha = rs_k / (pap_tot + 1e-12f);
        {
            float rp = 0.f;
            for (int i = t; i < 1024; i += 512) {
                sX[i] = fmaf(alpha, sP[ownOff + i], sX[i]);
                float rv = fmaf(-alpha, sAp[i], sR[i]);
                sR[i] = rv;
                rp = fmaf(rv, rv, rp);
            }
            rp = warp_sum(rp);
            if (lane == 0) sRed[wid] = rp;
        }
        __syncthreads();
        if (t < 8) {
            float tot = 0.f;
#pragma unroll
            for (int j = 0; j < 16; j++) tot += sRed[j];
            st_remote(aS0, (unsigned)t, tot);
        }
        if (c > 0 && t < 32)              st_remote(aHR + t*4, (unsigned)(c-1), sR[t]);
        if (c < 7 && t >= 32 && t < 64) { int l = t - 32;
                                          st_remote(aHL + l*4, (unsigned)(c+1), sR[31*32 + l]); }
        rs_prev = rs_k;
        cluster_sync_();
    }

    // final x -> g_c and out c segment
    for (int i = t; i < 1024; i += 512) {
        float v = sX[i];
        int o = (b*Mm + m0)*32 + i;
        g_c[o] = v;
        out[Bb*Qq + Bb*Mm*Dd + o] = v;
    }
}

// ---------------- kernel 3: sparse decode (3-neighborhood) ------------------
__global__ __launch_bounds__(256) void dec_kernel(
    const float* __restrict__ phi, const float* __restrict__ w,
    float* __restrict__ out)
{
    __shared__ float sc[3*8*32];
    __shared__ float sw[3*32];
    int blk = blockIdx.x, t = threadIdx.x;
    int q0 = blk * 32;
    int g = blk >> 1;                  // 64-q group shares an m-center
    int mlist[3]; int nm = 0;
#pragma unroll
    for (int dm = -1; dm <= 1; dm++) {
        int mm = g + dm;
        if (mm >= 0 && mm < Mm) mlist[nm++] = mm;
    }
    for (int i = t; i < nm*256; i += 256) {
        int mi = i >> 8, rem = i & 255;
        int bidx = rem >> 5, d = rem & 31;
        sc[i] = g_c[(bidx*Mm + mlist[mi])*Dd + d];
    }
    if (t < nm*32) {
        int mi = t >> 5, ql = t & 31;
        sw[t] = w[mlist[mi]*Qq + q0 + ql];
    }
    __syncthreads();

    int ql = t >> 3, dq = t & 7;       // 8 threads per q, 4 d each
    int q = q0 + ql;
    float s[8];
#pragma unroll
    for (int bidx = 0; bidx < 8; bidx++) s[bidx] = 0.f;

    for (int mi = 0; mi < nm; mi++) {
        const float* ph = phi + ((size_t)mlist[mi]*Qq + q)*Dd + dq*4;
        float4 p0 = *(const float4*)ph;
        float wq = sw[mi*32 + ql];
#pragma unroll
        for (int bidx = 0; bidx < 8; bidx++) {
            const float* cc = &sc[(mi*8 + bidx)*32 + dq*4];
            float dot = p0.x*cc[0] + p0.y*cc[1] + p0.z*cc[2] + p0.w*cc[3];
            s[bidx] = fmaf(wq, dot, s[bidx]);
        }
    }
#pragma unroll
    for (int bidx = 0; bidx < 8; bidx++) {
        s[bidx] += __shfl_xor_sync(0xffffffffu, s[bidx], 1);
        s[bidx] += __shfl_xor_sync(0xffffffffu, s[bidx], 2);
        s[bidx] += __shfl_xor_sync(0xffffffffu, s[bidx], 4);
    }
    if (dq == 0) {
#pragma unroll
        for (int bidx = 0; bidx < 8; bidx++)
            out[bidx*Qq + q] = s[bidx];
    }
}

// ---------------- launch ----------------------------------------------------
extern "C" void kernel_launch(void* const* d_in, const int* in_sizes, int n_in,
                              void* d_out, int out_size)
{
    (void)in_sizes; (void)n_in; (void)out_size;
    const float* xs      = (const float*)d_in[0];
    const float* us      = (const float*)d_in[1];
    const float* phi     = (const float*)d_in[2];
    const float* w       = (const float*)d_in[3];
    const float* centers = (const float*)d_in[4];
    const float* Rsrc    = (const float*)d_in[5];
    const float* Rdst    = (const float*)d_in[6];
    const float* W1      = (const float*)d_in[7];
    const float* b1      = (const float*)d_in[8];
    const float* W2      = (const float*)d_in[9];
    const float* b2      = (const float*)d_in[10];
    const float* W3      = (const float*)d_in[11];
    const float* b3      = (const float*)d_in[12];
    const float* Wg1     = (const float*)d_in[13];
    const float* bg1     = (const float*)d_in[14];
    const float* Wg2     = (const float*)d_in[15];
    const float* bg2     = (const float*)d_in[16];
    const int*   idx     = (const int*)d_in[17];
    float* out = (float*)d_out;

    cudaFuncSetAttribute(cg_kernel, cudaFuncAttributeMaxDynamicSharedMemorySize,
                         SMEM_CG_BYTES);

    fe_kernel<<<8 + Mm*Bb/4, 256>>>(xs, us, centers, idx,
                                    W1, b1, W2, b2, W3, b3,
                                    Wg1, bg1, Wg2, bg2);
    cg_kernel<<<64, 512, SMEM_CG_BYTES>>>(Rsrc, Rdst, out);
    dec_kernel<<<Qq/32, 256>>>(phi, w, out);
}

// round 10
// speedup vs baseline: 1.3433x; 1.3433x over previous
#include <cuda_runtime.h>
#include <cstdint>

#define Bb 8
#define Nn 2048
#define Mm 256
#define Qq 16384
#define Dd 32
#define Rr 16
#define Kk 16
#define Hh 64
#define LAM 5.0f
#define NITER 20
#define RAD 0.005859375f   // 1.5/256 exact in binary

// ---------------- scratch (device globals; no allocation allowed) ----------
__device__ float g_c0[Bb*Mm*Dd];
__device__ float g_c [Bb*Mm*Dd];
__device__ float g_gvec[Bb*Dd];

__device__ __forceinline__ float warp_sum(float v) {
#pragma unroll
    for (int o = 16; o; o >>= 1) v += __shfl_xor_sync(0xffffffffu, v, o);
    return v;
}

__device__ __forceinline__ unsigned smem_u32(const void* p) {
    unsigned a;
    asm("{ .reg .u64 t; cvta.to.shared.u64 t, %1; cvt.u32.u64 %0, t; }"
        : "=r"(a) : "l"(p));
    return a;
}

// store 4 bytes into peer CTA (rank) smem at the address corresponding to laddr
__device__ __forceinline__ void st_remote(unsigned laddr, unsigned rank, float v) {
    unsigned r;
    asm volatile("mapa.shared::cluster.u32 %0, %1, %2;" : "=r"(r) : "r"(laddr), "r"(rank));
    asm volatile("st.shared::cluster.f32 [%0], %1;" :: "r"(r), "f"(v) : "memory");
}

__device__ __forceinline__ void cluster_sync_() {
    asm volatile("barrier.cluster.arrive.aligned;" ::: "memory");  // release
    asm volatile("barrier.cluster.wait.aligned;"   ::: "memory");  // acquire
}

// ---------------- kernel 1: global gate vector gvec[b][d] -------------------
__global__ __launch_bounds__(256) void gvec_kernel(
    const float* __restrict__ xs, const float* __restrict__ us,
    const float* __restrict__ Wg1, const float* __restrict__ bg1,
    const float* __restrict__ Wg2, const float* __restrict__ bg2)
{
    __shared__ float sp[4*Hh];
    __shared__ float sg[Hh];
    int b = blockIdx.x, t = threadIdx.x;
    int h = t & 63, grp = t >> 6;
    float w0 = Wg1[h], w1 = Wg1[Hh+h], bb = bg1[h];
    const float* xp = xs + b*Nn;
    const float* up = us + b*Nn;
    float acc = 0.f;
    int n0 = grp * (Nn/4);
    for (int n = n0; n < n0 + Nn/4; n++)
        acc += fmaxf(fmaf(xp[n], w0, fmaf(up[n], w1, bb)), 0.f);
    sp[t] = acc;
    __syncthreads();
    if (t < Hh) sg[t] = (sp[t] + sp[64+t] + sp[128+t] + sp[192+t]) * (1.0f/Nn);
    __syncthreads();
    if (t < Dd) {
        float a = bg2[t];
        for (int hh = 0; hh < Hh; hh++) a = fmaf(sg[hh], Wg2[hh*Dd + t], a);
        g_gvec[b*Dd + t] = a;
    }
}

// ---------------- kernel 2: encoder (low-smem; W2 from L1-resident gmem) ----
__global__ __launch_bounds__(64) void enc_kernel(
    const float* __restrict__ xs, const float* __restrict__ us,
    const float* __restrict__ centers, const int* __restrict__ idx,
    const float* __restrict__ W1, const float* __restrict__ b1,
    const float* __restrict__ W2, const float* __restrict__ b2,
    const float* __restrict__ W3, const float* __restrict__ b3,
    float* __restrict__ out)
{
    __shared__ float sh1[16*68];    // h1[k][i], float4-aligned rows
    __shared__ float srel[16], su[16], sW1[128], shbar[64];
    int m = blockIdx.x, b = blockIdx.y, t = threadIdx.x;

    for (int i = t; i < 128; i += 64) sW1[i] = W1[i];
    if (t < 16) {
        int sidx = idx[m*Kk + t];
        srel[t] = (xs[b*Nn + sidx] - centers[m]) / RAD;
        su[t]   = us[b*Nn + sidx];
    }
    __syncthreads();

    {   // h1: thread t = hidden unit i
        float wa = sW1[t], wb = sW1[64+t], bb = b1[t];
#pragma unroll
        for (int k = 0; k < 16; k++)
            sh1[k*68 + t] = fmaxf(fmaf(srel[k], wa, fmaf(su[k], wb, bb)), 0.f);
    }
    __syncthreads();

    {   // h2 = relu(h1 @ W2 + b2); mean over k.  W2 columns via coalesced LDG.
        float acc[16];
        float bb = b2[t];
#pragma unroll
        for (int k = 0; k < 16; k++) acc[k] = bb;
#pragma unroll 4
        for (int i = 0; i < 64; i += 4) {
            float w0 = __ldg(&W2[(i+0)*64 + t]);
            float w1 = __ldg(&W2[(i+1)*64 + t]);
            float w2 = __ldg(&W2[(i+2)*64 + t]);
            float w3 = __ldg(&W2[(i+3)*64 + t]);
#pragma unroll
            for (int k = 0; k < 16; k++) {
                float4 hq = *(const float4*)&sh1[k*68 + i];
                acc[k] = fmaf(hq.x, w0, acc[k]);
                acc[k] = fmaf(hq.y, w1, acc[k]);
                acc[k] = fmaf(hq.z, w2, acc[k]);
                acc[k] = fmaf(hq.w, w3, acc[k]);
            }
        }
        float s = 0.f;
#pragma unroll
        for (int k = 0; k < 16; k++) s += fmaxf(acc[k], 0.f);
        shbar[t] = s * 0.0625f;
    }
    __syncthreads();

    if (t < 32) {
        float v = b3[t];
        for (int j = 0; j < 64; j++) v = fmaf(shbar[j], W3[j*Dd + t], v);
        v += g_gvec[b*Dd + t];
        int o = (b*Mm + m)*Dd + t;
        g_c0[o] = v;
        out[Bb*Qq + o] = v;   // c0 output segment
    }
}

// ---------------- CG: sheaf Laplacian edge pass (R tiles in smem) -----------
// 16-warp stride version of the R8 edge pass (phase1 rows + phase2 columns,
// both from padded smem; no register columns).
__device__ __forceinline__ void edge_pass(
    const float* __restrict__ sRS, const float* __restrict__ sRD,
    const float* __restrict__ sP, float* __restrict__ sGs, float* __restrict__ sGd,
    float* __restrict__ sRe, int nE, int wid, int lane)
{
    int rho = lane >> 1, h = lane & 1;
    int d = lane;
    for (int el = wid; el < nE; el += 16) {
        const float* bs = sRS + el*528;
        const float* bd = sRD + el*528;
        const float* ps = sP + el*32 + 16*h;     // src half; dst at +32
        const float* rs_ = bs + rho*33 + 16*h;
        const float* rd_ = bd + rho*33 + 16*h;
        float a0 = 0.f, a1 = 0.f, a2 = 0.f, a3 = 0.f;
#pragma unroll
        for (int i = 0; i < 16; i += 4) {
            a0 = fmaf(rs_[i+0], ps[i+0], a0);
            a1 = fmaf(rs_[i+1], ps[i+1], a1);
            a2 = fmaf(rs_[i+2], ps[i+2], a2);
            a3 = fmaf(rs_[i+3], ps[i+3], a3);
            a0 = fmaf(rd_[i+0], -ps[32+i+0], a0);
            a1 = fmaf(rd_[i+1], -ps[32+i+1], a1);
            a2 = fmaf(rd_[i+2], -ps[32+i+2], a2);
            a3 = fmaf(rd_[i+3], -ps[32+i+3], a3);
        }
        float acc = (a0 + a1) + (a2 + a3);
        acc += __shfl_xor_sync(0xffffffffu, acc, 1);
        if (h == 0) sRe[el*16 + rho] = acc;
        __syncwarp();

        float g0 = 0.f, g1 = 0.f, q0a = 0.f, q1a = 0.f;
#pragma unroll
        for (int q = 0; q < 16; q += 2) {
            float r0v = sRe[el*16 + q];
            float r1v = sRe[el*16 + q + 1];
            g0  = fmaf(bs[q*33 + d],       r0v, g0);
            g1  = fmaf(bs[(q+1)*33 + d],   r1v, g1);
            q0a = fmaf(bd[q*33 + d],       r0v, q0a);
            q1a = fmaf(bd[(q+1)*33 + d],   r1v, q1a);
        }
        sGs[el*32 + d] = g0 + g1;
        sGd[el*32 + d] = q0a + q1a;
    }
}

// ---------------- kernel 3: persistent cluster CG (8 clusters x 8 CTAs) -----
// smem layout (float offsets)
#define SM_RS  0
#define SM_RD  17424
#define SM_P   (17424*2)          // 34848
#define SM_X   (SM_P + 1088)
#define SM_R   (SM_X + 1024)
#define SM_AP  (SM_R + 1024)
#define SM_GS  (SM_AP + 1024)     // 33*32
#define SM_GD  (SM_GS + 1056)
#define SM_RE  (SM_GD + 1056)     // 33*16
#define SM_RED (SM_RE + 528)      // 16 warp partials
#define SM_S0  (SM_RED + 16)      // incoming rs partials [8]
#define SM_S1  (SM_S0 + 8)        // incoming pAp partials [8]
#define SM_HL  (SM_S1 + 8)        // incoming left-halo r [32]
#define SM_HR  (SM_HL + 32)       // incoming right-halo r [32]
#define SM_TOT_FLOATS (SM_HR + 32)
#define SMEM_CG_BYTES (SM_TOT_FLOATS * 4)

__global__ __launch_bounds__(512, 1) __cluster_dims__(8, 1, 1)
void cg_kernel(const float* __restrict__ Rsrc, const float* __restrict__ Rdst,
               float* __restrict__ out)
{
    extern __shared__ float sm[];
    float* sRS  = sm + SM_RS;
    float* sRD  = sm + SM_RD;
    float* sP   = sm + SM_P;
    float* sX   = sm + SM_X;
    float* sR   = sm + SM_R;
    float* sAp  = sm + SM_AP;
    float* sGs  = sm + SM_GS;
    float* sGd  = sm + SM_GD;
    float* sRe  = sm + SM_RE;
    float* sRed = sm + SM_RED;
    float* sS0  = sm + SM_S0;
    float* sS1  = sm + SM_S1;
    float* sHL  = sm + SM_HL;
    float* sHR  = sm + SM_HR;

    int t = threadIdx.x, wid = t >> 5, lane = t & 31;
    int blk = blockIdx.x;
    int b = blk >> 3, c = blk & 7;          // cluster = batch, rank = c
    int m0 = c * 32;
    int mLo = (c > 0) ? m0 - 1 : 0;
    int mHi = (c < 7) ? m0 + 32 : 255;
    int nExt = mHi - mLo + 1;
    int eLo = (c > 0) ? m0 - 1 : 0;
    int eHi = (c < 7) ? m0 + 31 : 254;
    int nE = eHi - eLo + 1;
    int ownOff = (m0 - mLo) * 32;

    unsigned smb = smem_u32(sm);
    unsigned aS0 = smb + (SM_S0 + c) * 4;   // slot c in peers' rs array
    unsigned aS1 = smb + (SM_S1 + c) * 4;   // slot c in peers' pAp array
    unsigned aHL = smb + SM_HL * 4;
    unsigned aHR = smb + SM_HR * 4;

    // ---- load R tiles into padded smem (resident for all iterations) ----
    for (int i = t; i < nE*512; i += 512) {
        int el = i >> 9, rem = i & 511;
        int rho = rem >> 5, d = rem & 31;
        int g = (eLo + el)*512 + rem;
        sRS[el*528 + rho*33 + d] = Rsrc[g];
        sRD[el*528 + rho*33 + d] = Rdst[g];
    }
    const float* c0b = g_c0 + b*Mm*Dd;
    for (int i = t; i < nExt*32; i += 512) sP[i] = c0b[mLo*32 + i];
    __syncthreads();
    for (int i = t; i < 1024; i += 512) sX[i] = sP[ownOff + i];

    // ---- prologue: r0 = -LAM * L(c0) ----
    edge_pass(sRS, sRD, sP, sGs, sGd, sRe, nE, wid, lane);
    __syncthreads();
    {
        float part = 0.f;
        for (int i = t; i < 1024; i += 512) {
            int d = i & 31;
            int m = m0 + (i >> 5);
            float gs = (m <= 254) ? sGs[(m - eLo)*32 + d] : 0.f;
            float gd = (m >= 1)   ? sGd[(m - 1 - eLo)*32 + d] : 0.f;
            float rv = -LAM * (gs - gd);
            sR[i] = rv;
            part = fmaf(rv, rv, part);
        }
        part = warp_sum(part);
        if (lane == 0) sRed[wid] = part;
    }
    __syncthreads();
    // push rs partials to all ranks + r halos to neighbors
    if (t < 8) {
        float tot = 0.f;
#pragma unroll
        for (int j = 0; j < 16; j++) tot += sRed[j];
        st_remote(aS0, (unsigned)t, tot);
    }
    if (c > 0 && t < 32)              st_remote(aHR + t*4, (unsigned)(c-1), sR[t]);
    if (c < 7 && t >= 32 && t < 64) { int l = t - 32;
                                      st_remote(aHL + l*4, (unsigned)(c+1), sR[31*32 + l]); }
    cluster_sync_();

    float rs_prev = 1.f;
    for (int k = 0; k < NITER; k++) {
        // ---- phase A: beta, p update, Ap, partial p.Ap ----
        float rs_k = 0.f;
#pragma unroll
        for (int j = 0; j < 8; j++) rs_k += sS0[j];
        float beta = (k == 0) ? 0.f : rs_k / (rs_prev + 1e-12f);

        for (int i = t; i < 1024; i += 512)
            sP[ownOff + i] = fmaf(beta, sP[ownOff + i], sR[i]);
        if (c > 0 && t < 32)
            sP[t] = fmaf(beta, sP[t], sHL[t]);
        if (c < 7 && t >= 32 && t < 64) { int l = t - 32;
            sP[(nExt-1)*32 + l] = fmaf(beta, sP[(nExt-1)*32 + l], sHR[l]); }
        __syncthreads();
        edge_pass(sRS, sRD, sP, sGs, sGd, sRe, nE, wid, lane);
        __syncthreads();
        {
            float pap = 0.f;
            for (int i = t; i < 1024; i += 512) {
                int d = i & 31;
                int m = m0 + (i >> 5);
                float gs = (m <= 254) ? sGs[(m - eLo)*32 + d] : 0.f;
                float gd = (m >= 1)   ? sGd[(m - 1 - eLo)*32 + d] : 0.f;
                float pv = sP[ownOff + i];
                float ap = fmaf(LAM, gs - gd, pv);
                sAp[i] = ap;
                pap = fmaf(ap, pv, pap);
            }
            pap = warp_sum(pap);
            if (lane == 0) sRed[wid] = pap;
        }
        __syncthreads();
        if (t < 8) {
            float tot = 0.f;
#pragma unroll
            for (int j = 0; j < 16; j++) tot += sRed[j];
            st_remote(aS1, (unsigned)t, tot);
        }
        cluster_sync_();

        // ---- phase B: alpha, x/r update, partial ||r||^2, push rs + halo ----
        float pap_tot = 0.f;
#pragma unroll
        for (int j = 0; j < 8; j++) pap_tot += sS1[j];
        float alpha = rs_k / (pap_tot + 1e-12f);
        {
            float rp = 0.f;
            for (int i = t; i < 1024; i += 512) {
                sX[i] = fmaf(alpha, sP[ownOff + i], sX[i]);
                float rv = fmaf(-alpha, sAp[i], sR[i]);
                sR[i] = rv;
                rp = fmaf(rv, rv, rp);
            }
            rp = warp_sum(rp);
            if (lane == 0) sRed[wid] = rp;
        }
        __syncthreads();
        if (t < 8) {
            float tot = 0.f;
#pragma unroll
            for (int j = 0; j < 16; j++) tot += sRed[j];
            st_remote(aS0, (unsigned)t, tot);
        }
        if (c > 0 && t < 32)              st_remote(aHR + t*4, (unsigned)(c-1), sR[t]);
        if (c < 7 && t >= 32 && t < 64) { int l = t - 32;
                                          st_remote(aHL + l*4, (unsigned)(c+1), sR[31*32 + l]); }
        rs_prev = rs_k;
        cluster_sync_();
    }

    // final x -> g_c and out c segment
    for (int i = t; i < 1024; i += 512) {
        float v = sX[i];
        int o = (b*Mm + m0)*32 + i;
        g_c[o] = v;
        out[Bb*Qq + Bb*Mm*Dd + o] = v;
    }
}

// ---------------- kernel 4: sparse decode (3-neighborhood, 8 thr/q) ---------
__global__ __launch_bounds__(256) void dec_kernel(
    const float* __restrict__ phi, const float* __restrict__ w,
    float* __restrict__ out)
{
    __shared__ float sc[3*8*32];
    __shared__ float sw[3*32];
    int blk = blockIdx.x, t = threadIdx.x;
    int q0 = blk * 32;
    int g = blk >> 1;                  // 64-q group shares an m-center
    int mlist[3]; int nm = 0;
#pragma unroll
    for (int dm = -1; dm <= 1; dm++) {
        int mm = g + dm;
        if (mm >= 0 && mm < Mm) mlist[nm++] = mm;
    }
    for (int i = t; i < nm*256; i += 256) {
        int mi = i >> 8, rem = i & 255;
        int bidx = rem >> 5, d = rem & 31;
        sc[i] = g_c[(bidx*Mm + mlist[mi])*Dd + d];
    }
    if (t < nm*32) {
        int mi = t >> 5, ql = t & 31;
        sw[t] = w[mlist[mi]*Qq + q0 + ql];
    }
    __syncthreads();

    int ql = t >> 3, dq = t & 7;       // 8 threads per q, 4 d each
    int q = q0 + ql;
    float s[8];
#pragma unroll
    for (int bidx = 0; bidx < 8; bidx++) s[bidx] = 0.f;

    for (int mi = 0; mi < nm; mi++) {
        const float* ph = phi + ((size_t)mlist[mi]*Qq + q)*Dd + dq*4;
        float4 p0 = *(const float4*)ph;
        float wq = sw[mi*32 + ql];
#pragma unroll
        for (int bidx = 0; bidx < 8; bidx++) {
            const float* cc = &sc[(mi*8 + bidx)*32 + dq*4];
            float dot = p0.x*cc[0] + p0.y*cc[1] + p0.z*cc[2] + p0.w*cc[3];
            s[bidx] = fmaf(wq, dot, s[bidx]);
        }
    }
#pragma unroll
    for (int bidx = 0; bidx < 8; bidx++) {
        s[bidx] += __shfl_xor_sync(0xffffffffu, s[bidx], 1);
        s[bidx] += __shfl_xor_sync(0xffffffffu, s[bidx], 2);
        s[bidx] += __shfl_xor_sync(0xffffffffu, s[bidx], 4);
    }
    if (dq == 0) {
#pragma unroll
        for (int bidx = 0; bidx < 8; bidx++)
            out[bidx*Qq + q] = s[bidx];
    }
}

// ---------------- launch ----------------------------------------------------
extern "C" void kernel_launch(void* const* d_in, const int* in_sizes, int n_in,
                              void* d_out, int out_size)
{
    (void)in_sizes; (void)n_in; (void)out_size;
    const float* xs      = (const float*)d_in[0];
    const float* us      = (const float*)d_in[1];
    const float* phi     = (const float*)d_in[2];
    const float* w       = (const float*)d_in[3];
    const float* centers = (const float*)d_in[4];
    const float* Rsrc    = (const float*)d_in[5];
    const float* Rdst    = (const float*)d_in[6];
    const float* W1      = (const float*)d_in[7];
    const float* b1      = (const float*)d_in[8];
    const float* W2      = (const float*)d_in[9];
    const float* b2      = (const float*)d_in[10];
    const float* W3      = (const float*)d_in[11];
    const float* b3      = (const float*)d_in[12];
    const float* Wg1     = (const float*)d_in[13];
    const float* bg1     = (const float*)d_in[14];
    const float* Wg2     = (const float*)d_in[15];
    const float* bg2     = (const float*)d_in[16];
    const int*   idx     = (const int*)d_in[17];
    float* out = (float*)d_out;

    cudaFuncSetAttribute(cg_kernel, cudaFuncAttributeMaxDynamicSharedMemorySize,
                         SMEM_CG_BYTES);

    gvec_kernel<<<Bb, 256>>>(xs, us, Wg1, bg1, Wg2, bg2);
    enc_kernel<<<dim3(Mm, Bb), 64>>>(xs, us, centers, idx,
                                     W1, b1, W2, b2, W3, b3, out);
    cg_kernel<<<64, 512, SMEM_CG_BYTES>>>(Rsrc, Rdst, out);
    dec_kernel<<<Qq/32, 256>>>(phi, w, out);
}